// round 7
// baseline (speedup 1.0000x reference)
#include <cuda_runtime.h>

// DTM (distance-to-measure) on a 64x64 integer grid.
// Per (b,c) slice: bound = 0.05 * sum(w). Per point p: walk grid points in
// order of increasing squared distance, accumulate weight until crossing
// bound, output sqrt((sum_{d<d*} d^2 w + d*^2 (bound - cum_before)) / bound).
// Weights quantized to q = floor(w * 65535): we solve that perturbed problem
// EXACTLY in integers (result is scale-invariant in w, so rel err ~1e-5).
// With B = S/20 (S = sum of q): k = first prefix with 20*cum >= S, and
// dtm = sqrt(num / S), num = 20*sum_{i<k} d2_i q_i + d2_k*(S - 20 cum_{k-1}).

#define HW 4096
#define NSLICE 12
#define NOFF 16129            // (dy,dx) in [-63,63]^2
#define NMAIN 16128           // 126 batches of 128; 1 epilogue entry
#define PITCH 65
#define ZSLOT (64 * PITCH)    // guaranteed-zero slot for OOB entries
#define QS 65535.0f

// entry: d2 << 16 | (dy+64) << 8 | (dx+64)
__device__ __align__(16) unsigned g_tab[NOFF];

// ---- build: 4 lanes per offset compute its sorted rank in closed form ----

__global__ void __launch_bounds__(256) k_build() {
    int gid = blockIdx.x * 256 + threadIdx.x;
    int i = gid >> 2;
    int q = gid & 3;
    int dy = i / 127 - 63;
    int dx = i % 127 - 63;
    int d2 = dy * dy + dx * dx;
    int pos = 0;
    if (i < NOFF) {
        for (int a = q; a <= 63; a += 4) {  // +-a handled together
            int na = d2 - a * a;
            if (na < 0) break;
            int s = (int)sqrtf((float)na);  // exact floor at these magnitudes
            bool perf = (s * s == na);
            if (na > 0) {                   // # of b with b^2 < na, |b|<=63
                int tt = perf ? s - 1 : s;
                if (tt > 63) tt = 63;
                int cb = 2 * tt + 1;
                pos += (a == 0) ? cb : 2 * cb;
            }
            if (perf && s <= 63) {          // ties b = +-s, lex (a,b) order
                if (a < dy) pos += (s == 0) ? 1 : 2;
                else if (a == dy) {
                    if (-s < dx) pos++;
                    if (s != 0 && s < dx) pos++;
                }
                if (a != 0) {
                    int aa = -a;
                    if (aa < dy) pos += (s == 0) ? 1 : 2;
                    else if (aa == dy) {
                        if (-s < dx) pos++;
                        if (s != 0 && s < dx) pos++;
                    }
                }
            }
        }
    }
    pos += __shfl_xor_sync(~0u, pos, 1);
    pos += __shfl_xor_sync(~0u, pos, 2);
    if (q == 0 && i < NOFF) {
        g_tab[pos] = ((unsigned)d2 << 16) | ((unsigned)(dy + 64) << 8) |
                     (unsigned)(dx + 64);
    }
}

// ---- main: one warp per point, 128 sorted entries per step (4/lane) ----

__global__ void __launch_bounds__(1024, 2)
k_main(const float* __restrict__ x, float* __restrict__ out) {
    __shared__ int swq[ZSLOT + 1];  // 65-pitch quantized weights + zero slot
    __shared__ int sred[32];
    __shared__ int sS;

    int t = threadIdx.x;
    int slice = blockIdx.x >> 7;   // 128 point-groups of 32 per slice
    int pg = blockIdx.x & 127;
    const float4* src4 = (const float4*)(x + slice * HW);

    if (t == 0) swq[ZSLOT] = 0;
    // 4 contiguous cells per thread (never crosses a row)
    float4 v = src4[t];
    int cell = t * 4;
    int rb = (cell >> 6) * PITCH + (cell & 63);
    int q0 = (int)(v.x * QS), q1 = (int)(v.y * QS);
    int q2 = (int)(v.z * QS), q3 = (int)(v.w * QS);
    swq[rb + 0] = q0; swq[rb + 1] = q1; swq[rb + 2] = q2; swq[rb + 3] = q3;
    int ls = (q0 + q1) + (q2 + q3);
#pragma unroll
    for (int o = 16; o; o >>= 1) ls += __shfl_xor_sync(~0u, ls, o);
    if ((t & 31) == 0) sred[t >> 5] = ls;
    __syncthreads();
    if (t == 0) {
        int S = 0;
#pragma unroll
        for (int k = 0; k < 32; k++) S += sred[k];
        sS = S;
    }
    __syncthreads();
    int S = sS;
    int Bc = (S + 19) / 20;  // crossing: first integer cum >= ceil(S/20)

    int w = t >> 5;
    int lane = t & 31;
    int p = (pg << 5) + w;
    int row = p >> 6;
    int col = p & 63;
    unsigned pb = ((unsigned)row << 8) | (unsigned)col;

    int cum = 0;                  // warp-uniform exact integer running sum
    unsigned long long acc = 0;   // per-lane distributed sum of d2*q
    unsigned long long num = 0;
    int crossed = 0;

    const uint4* tp = (const uint4*)g_tab;  // uint4 = 4 entries

    for (int base = 0; base < NMAIN; base += 128) {
        uint4 c = __ldg(tp + (base >> 2) + lane);
        // SWAR: S = low16 + pb; valid <=> (S & 0xC0C0) == 0x4040 (no carries)
        // index = (S>>8)*65 + (S&255) - 4224  (= (row+dy)*65 + (col+dx))
        unsigned s0 = (c.x & 0xFFFFu) + pb;
        int i0 = ((s0 & 0xC0C0u) == 0x4040u)
                     ? (int)((s0 >> 8) * 65u + (s0 & 255u)) - 4224 : ZSLOT;
        unsigned s1 = (c.y & 0xFFFFu) + pb;
        int i1 = ((s1 & 0xC0C0u) == 0x4040u)
                     ? (int)((s1 >> 8) * 65u + (s1 & 255u)) - 4224 : ZSLOT;
        unsigned s2 = (c.z & 0xFFFFu) + pb;
        int i2 = ((s2 & 0xC0C0u) == 0x4040u)
                     ? (int)((s2 >> 8) * 65u + (s2 & 255u)) - 4224 : ZSLOT;
        unsigned s3 = (c.w & 0xFFFFu) + pb;
        int i3 = ((s3 & 0xC0C0u) == 0x4040u)
                     ? (int)((s3 >> 8) * 65u + (s3 & 255u)) - 4224 : ZSLOT;
        int w0 = swq[i0], w1 = swq[i1], w2 = swq[i2], w3 = swq[i3];
        int d0 = (int)(c.x >> 16), d1 = (int)(c.y >> 16);
        int d2v = (int)(c.z >> 16), d3 = (int)(c.w >> 16);

        int mi = (w0 + w1) + (w2 + w3);
        int tot = __reduce_add_sync(~0u, mi);  // all lanes get the sum

        if (cum + tot >= Bc) {  // warp-uniform, exact
            // ordered resolve (once per point)
            int s = mi;
#pragma unroll
            for (int o = 1; o < 32; o <<= 1) {
                int u = __shfl_up_sync(~0u, s, o);
                if (lane >= o) s += u;
            }
            int b0 = cum + s - mi;  // exact cum before this lane's entries
            int e1 = b0 + w0, e2 = e1 + w1, e3 = e2 + w2, e4 = e3 + w3;
            unsigned m = __ballot_sync(~0u, e4 >= Bc);  // bit31 guaranteed
            int fl = __ffs(m) - 1;
            unsigned long long part = 0;
            if (lane < fl) {
                acc += (unsigned long long)(unsigned)(d0 * w0);
                acc += (unsigned long long)(unsigned)(d1 * w1);
                acc += (unsigned long long)(unsigned)(d2v * w2);
                acc += (unsigned long long)(unsigned)(d3 * w3);
            } else if (lane == fl) {
                if (e1 >= Bc) {
                    part = (unsigned long long)d0 * (unsigned)(S - 20 * b0);
                } else {
                    acc += (unsigned long long)(unsigned)(d0 * w0);
                    if (e2 >= Bc) {
                        part = (unsigned long long)d1 * (unsigned)(S - 20 * e1);
                    } else {
                        acc += (unsigned long long)(unsigned)(d1 * w1);
                        if (e3 >= Bc) {
                            part = (unsigned long long)d2v *
                                   (unsigned)(S - 20 * e2);
                        } else {
                            acc += (unsigned long long)(unsigned)(d2v * w2);
                            part = (unsigned long long)d3 *
                                   (unsigned)(S - 20 * e3);
                        }
                    }
                }
            }
            num = acc * 20ull + part;
            crossed = 1;
            break;  // warp-uniform exit
        }
        cum += tot;
        acc += (unsigned long long)(unsigned)(d0 * w0);
        acc += (unsigned long long)(unsigned)(d1 * w1);
        acc += (unsigned long long)(unsigned)(d2v * w2);
        acc += (unsigned long long)(unsigned)(d3 * w3);
    }

    if (!crossed) {  // essentially never: resolve on the single last entry
        unsigned e = g_tab[NMAIN];
        int dd = (int)(e >> 16);
        int rem = S - 20 * cum;
        if (rem < 0) rem = 0;
        num = acc * 20ull +
              (lane == 0 ? (unsigned long long)dd * (unsigned)rem : 0ull);
    }

#pragma unroll
    for (int o = 16; o; o >>= 1) num += __shfl_xor_sync(~0u, num, o);
    if (lane == 0)
        out[slice * HW + p] = (float)sqrt((double)num / (double)S);
}

extern "C" void kernel_launch(void* const* d_in, const int* in_sizes, int n_in,
                              void* d_out, int out_size) {
    const float* x = (const float*)d_in[0];
    float* out = (float*)d_out;

    k_build<<<(NOFF * 4 + 255) / 256, 256>>>();
    k_main<<<NSLICE * 128, 1024>>>(x, out);
}

// round 8
// speedup vs baseline: 1.0531x; 1.0531x over previous
#include <cuda_runtime.h>

// DTM (distance-to-measure) on a 64x64 integer grid.
// Per (b,c) slice: bound = 0.05 * sum(w). Per point p: walk grid points in
// order of increasing squared distance, accumulate weight until crossing
// bound, output sqrt((sum_{d<d*} d^2 w + d*^2 (bound - cum_before)) / bound).
// Weights quantized to q = floor(w * 65535): we solve that perturbed problem
// EXACTLY in integers (result is scale-invariant in w, so rel err ~1e-5).
// With B = S/20 (S = sum of q): k = first prefix with 20*cum >= S, and
// dtm = sqrt(num / S), num = 20*sum_{i<k} d2_i q_i + d2_k*(S - 20 cum_{k-1}).

#define HW 4096
#define NSLICE 12
#define NOFF 16129            // (dy,dx) in [-63,63]^2
#define NMAIN 16128           // 126 batches of 128; 1 epilogue entry
#define PITCH 65
#define ZSLOT (64 * PITCH)    // guaranteed-zero slot for OOB entries
#define QS 65535.0f

// entry: d2 << 16 | (dy+64) << 8 | (dx+64)
__device__ __align__(16) unsigned g_tab[NOFF];

// ---- build: 8 lanes per offset compute its sorted rank in closed form ----

__global__ void __launch_bounds__(256) k_build() {
    int gid = blockIdx.x * 256 + threadIdx.x;
    int i = gid >> 3;
    int q = gid & 7;
    int dy = i / 127 - 63;
    int dx = i % 127 - 63;
    int d2 = dy * dy + dx * dx;
    int pos = 0;
    if (i < NOFF) {
        for (int a = q; a <= 63; a += 8) {  // +-a handled together
            int na = d2 - a * a;
            if (na < 0) break;
            int s = (int)sqrtf((float)na);  // exact floor at these magnitudes
            bool perf = (s * s == na);
            if (na > 0) {                   // # of b with b^2 < na, |b|<=63
                int tt = perf ? s - 1 : s;
                if (tt > 63) tt = 63;
                int cb = 2 * tt + 1;
                pos += (a == 0) ? cb : 2 * cb;
            }
            if (perf && s <= 63) {          // ties b = +-s, lex (a,b) order
                if (a < dy) pos += (s == 0) ? 1 : 2;
                else if (a == dy) {
                    if (-s < dx) pos++;
                    if (s != 0 && s < dx) pos++;
                }
                if (a != 0) {
                    int aa = -a;
                    if (aa < dy) pos += (s == 0) ? 1 : 2;
                    else if (aa == dy) {
                        if (-s < dx) pos++;
                        if (s != 0 && s < dx) pos++;
                    }
                }
            }
        }
    }
    pos += __shfl_xor_sync(~0u, pos, 1);
    pos += __shfl_xor_sync(~0u, pos, 2);
    pos += __shfl_xor_sync(~0u, pos, 4);
    if (q == 0 && i < NOFF) {
        g_tab[pos] = ((unsigned)d2 << 16) | ((unsigned)(dy + 64) << 8) |
                     (unsigned)(dx + 64);
    }
}

// ---- main: one warp per point, 128 sorted entries per step (4/lane) ----

__global__ void __launch_bounds__(512, 3)
k_main(const float* __restrict__ x, float* __restrict__ out) {
    __shared__ int swq[ZSLOT + 1];  // 65-pitch quantized weights + zero slot
    __shared__ int sred[16];
    __shared__ int sS;

    int t = threadIdx.x;
    int slice = blockIdx.x >> 8;   // 256 point-groups of 16 per slice
    int pg = blockIdx.x & 255;
    const float4* src4 = (const float4*)(x + slice * HW);

    if (t == 0) swq[ZSLOT] = 0;
    // 8 contiguous cells per thread (never crosses a row)
    float4 v0 = src4[t * 2];
    float4 v1 = src4[t * 2 + 1];
    int cell = t * 8;
    int rb = (cell >> 6) * PITCH + (cell & 63);
    int q0 = (int)(v0.x * QS), q1 = (int)(v0.y * QS);
    int q2 = (int)(v0.z * QS), q3 = (int)(v0.w * QS);
    int q4 = (int)(v1.x * QS), q5 = (int)(v1.y * QS);
    int q6 = (int)(v1.z * QS), q7 = (int)(v1.w * QS);
    swq[rb + 0] = q0; swq[rb + 1] = q1; swq[rb + 2] = q2; swq[rb + 3] = q3;
    swq[rb + 4] = q4; swq[rb + 5] = q5; swq[rb + 6] = q6; swq[rb + 7] = q7;
    int ls = ((q0 + q1) + (q2 + q3)) + ((q4 + q5) + (q6 + q7));
#pragma unroll
    for (int o = 16; o; o >>= 1) ls += __shfl_xor_sync(~0u, ls, o);
    if ((t & 31) == 0) sred[t >> 5] = ls;
    __syncthreads();
    if (t == 0) {
        int S = 0;
#pragma unroll
        for (int k = 0; k < 16; k++) S += sred[k];
        sS = S;
    }
    __syncthreads();
    int S = sS;
    int Bc = (S + 19) / 20;  // crossing: first integer cum >= ceil(S/20)

    int w = t >> 5;
    int lane = t & 31;
    int p = (pg << 4) + w;
    int row = p >> 6;
    int col = p & 63;
    unsigned pb = ((unsigned)row << 8) | (unsigned)col;

    int cum = 0;                  // warp-uniform exact integer running sum
    unsigned long long acc = 0;   // per-lane distributed sum of d2*q
    unsigned long long num = 0;
    int crossed = 0;

    const uint4* tp = (const uint4*)g_tab;  // uint4 = 4 entries
    uint4 c = __ldg(tp + lane);             // prefetched batch

    for (int base = 0; base < NMAIN; base += 128) {
        uint4 nx = (base + 128 < NMAIN) ? __ldg(tp + ((base + 128) >> 2) + lane)
                                        : c;
        // SWAR: S = low16 + pb; valid <=> (S & 0xC0C0) == 0x4040 (no carries)
        // index = (S>>8)*65 + (S&255) - 4224  (= (row+dy)*65 + (col+dx))
        unsigned s0 = (c.x & 0xFFFFu) + pb;
        int i0 = ((s0 & 0xC0C0u) == 0x4040u)
                     ? (int)((s0 >> 8) * 65u + (s0 & 255u)) - 4224 : ZSLOT;
        unsigned s1 = (c.y & 0xFFFFu) + pb;
        int i1 = ((s1 & 0xC0C0u) == 0x4040u)
                     ? (int)((s1 >> 8) * 65u + (s1 & 255u)) - 4224 : ZSLOT;
        unsigned s2 = (c.z & 0xFFFFu) + pb;
        int i2 = ((s2 & 0xC0C0u) == 0x4040u)
                     ? (int)((s2 >> 8) * 65u + (s2 & 255u)) - 4224 : ZSLOT;
        unsigned s3 = (c.w & 0xFFFFu) + pb;
        int i3 = ((s3 & 0xC0C0u) == 0x4040u)
                     ? (int)((s3 >> 8) * 65u + (s3 & 255u)) - 4224 : ZSLOT;
        int w0 = swq[i0], w1 = swq[i1], w2 = swq[i2], w3 = swq[i3];
        int d0 = (int)(c.x >> 16), d1 = (int)(c.y >> 16);
        int d2v = (int)(c.z >> 16), d3 = (int)(c.w >> 16);

        int mi = (w0 + w1) + (w2 + w3);
        int tot = __reduce_add_sync(~0u, mi);  // all lanes get the sum

        if (cum + tot >= Bc) {  // warp-uniform, exact
            // ordered resolve (once per point)
            int s = mi;
#pragma unroll
            for (int o = 1; o < 32; o <<= 1) {
                int u = __shfl_up_sync(~0u, s, o);
                if (lane >= o) s += u;
            }
            int b0 = cum + s - mi;  // exact cum before this lane's entries
            int e1 = b0 + w0, e2 = e1 + w1, e3 = e2 + w2, e4 = e3 + w3;
            unsigned m = __ballot_sync(~0u, e4 >= Bc);  // bit31 guaranteed
            int fl = __ffs(m) - 1;
            unsigned long long part = 0;
            if (lane < fl) {
                acc += (unsigned long long)(unsigned)(d0 * w0);
                acc += (unsigned long long)(unsigned)(d1 * w1);
                acc += (unsigned long long)(unsigned)(d2v * w2);
                acc += (unsigned long long)(unsigned)(d3 * w3);
            } else if (lane == fl) {
                if (e1 >= Bc) {
                    part = (unsigned long long)d0 * (unsigned)(S - 20 * b0);
                } else {
                    acc += (unsigned long long)(unsigned)(d0 * w0);
                    if (e2 >= Bc) {
                        part = (unsigned long long)d1 * (unsigned)(S - 20 * e1);
                    } else {
                        acc += (unsigned long long)(unsigned)(d1 * w1);
                        if (e3 >= Bc) {
                            part = (unsigned long long)d2v *
                                   (unsigned)(S - 20 * e2);
                        } else {
                            acc += (unsigned long long)(unsigned)(d2v * w2);
                            part = (unsigned long long)d3 *
                                   (unsigned)(S - 20 * e3);
                        }
                    }
                }
            }
            num = acc * 20ull + part;
            crossed = 1;
            break;  // warp-uniform exit
        }
        cum += tot;
        acc += (unsigned long long)(unsigned)(d0 * w0);
        acc += (unsigned long long)(unsigned)(d1 * w1);
        acc += (unsigned long long)(unsigned)(d2v * w2);
        acc += (unsigned long long)(unsigned)(d3 * w3);
        c = nx;
    }

    if (!crossed) {  // essentially never: resolve on the single last entry
        unsigned e = g_tab[NMAIN];
        int dd = (int)(e >> 16);
        int rem = S - 20 * cum;
        if (rem < 0) rem = 0;
        num = acc * 20ull +
              (lane == 0 ? (unsigned long long)dd * (unsigned)rem : 0ull);
    }

#pragma unroll
    for (int o = 16; o; o >>= 1) num += __shfl_xor_sync(~0u, num, o);
    if (lane == 0)
        out[slice * HW + p] = (float)sqrt((double)num / (double)S);
}

extern "C" void kernel_launch(void* const* d_in, const int* in_sizes, int n_in,
                              void* d_out, int out_size) {
    const float* x = (const float*)d_in[0];
    float* out = (float*)d_out;

    k_build<<<(NOFF * 8 + 255) / 256, 256>>>();
    k_main<<<NSLICE * 256, 512>>>(x, out);
}

// round 9
// speedup vs baseline: 1.4970x; 1.4215x over previous
#include <cuda_runtime.h>

// DTM (distance-to-measure) on a 64x64 integer grid.
// Per (b,c) slice: bound = 0.05 * sum(w). Per point p: walk grid points in
// order of increasing squared distance, accumulate weight until crossing
// bound, output sqrt((sum_{d<d*} d^2 w + d*^2 (bound - cum_before)) / bound).
// Weights are quantized to 2^-18 (exactly-perturbed problem; result is
// scale-invariant in w, so rel error ~2^-18 << 1e-3 tolerance). Crossing
// detection runs on exact integer sums via REDUX; value resolution uses the
// float images of the quantized weights.

#define HW 4096
#define NSLICE 12
#define NOFF 16129            // (dy,dx) in [-63,63]^2
#define NPAD 16256            // multiple of 128 (127 batches)
#define PITCH 65
#define ZSLOT (64 * PITCH)    // guaranteed-zero slot for OOB entries
#define QSCALE 262144.0f      // 2^18

// entry: .x = (dy*65+dx)<<16 | (dy+64)<<8 | (dx+64);  .y = float(d2) bits
__device__ __align__(16) uint2 g_tab[NPAD];

// ---- build: 8 lanes per offset compute its sorted rank in closed form ----

__global__ void __launch_bounds__(256) k_build() {
    int gid = blockIdx.x * 256 + threadIdx.x;  // gid < 8*NPAD
    int i = gid >> 3;
    int q = gid & 7;
    int dy = i / 127 - 63;
    int dx = i % 127 - 63;
    int d2 = dy * dy + dx * dx;
    int pos = 0;
    if (i < NOFF) {
        for (int a = q; a <= 63; a += 8) {  // +-a handled together
            int na = d2 - a * a;
            if (na < 0) break;
            int s = (int)sqrtf((float)na);  // exact floor at these magnitudes
            bool perf = (s * s == na);
            if (na > 0) {                   // # of b with b^2 < na, |b|<=63
                int tt = perf ? s - 1 : s;
                if (tt > 63) tt = 63;
                int cb = 2 * tt + 1;
                pos += (a == 0) ? cb : 2 * cb;
            }
            if (perf && s <= 63) {          // ties b = +-s, lex (a,b) order
                if (a < dy) pos += (s == 0) ? 1 : 2;
                else if (a == dy) {
                    if (-s < dx) pos++;
                    if (s != 0 && s < dx) pos++;
                }
                if (a != 0) {
                    int aa = -a;
                    if (aa < dy) pos += (s == 0) ? 1 : 2;
                    else if (aa == dy) {
                        if (-s < dx) pos++;
                        if (s != 0 && s < dx) pos++;
                    }
                }
            }
        }
    }
    pos += __shfl_xor_sync(~0u, pos, 1);
    pos += __shfl_xor_sync(~0u, pos, 2);
    pos += __shfl_xor_sync(~0u, pos, 4);
    if (q == 0) {
        if (i >= NOFF) {
            if (i < NPAD) g_tab[i] = make_uint2(0u, 0u);  // pad: fails SWAR
        } else {
            int off = dy * PITCH + dx;
            unsigned vp = ((unsigned)(dy + 64) << 8) | (unsigned)(dx + 64);
            g_tab[pos] = make_uint2(((unsigned)(off & 0xFFFF) << 16) | vp,
                                    __float_as_uint((float)d2));
        }
    }
}

// ---- main: one warp per point, 128 sorted entries per step (4/lane) ----

__global__ void __launch_bounds__(512, 3)
k_main(const float* __restrict__ x, float* __restrict__ out) {
    __shared__ int swq[ZSLOT + 1];
    __shared__ int sredi[16];
    __shared__ float sboundf;
    __shared__ int sboundi;

    int t = threadIdx.x;
    int slice = blockIdx.x >> 8;   // 256 point-groups of 16 per slice
    int pg = blockIdx.x & 255;
    const float4* src4 = (const float4*)(x + slice * HW);

    if (t == 0) swq[ZSLOT] = 0;
    // 8 contiguous cells per thread (never crosses a row)
    float4 v0 = src4[t * 2];
    float4 v1 = src4[t * 2 + 1];
    int cb = t * 8;
    int rb = (cb >> 6) * PITCH + (cb & 63);
    int q0 = (int)(v0.x * QSCALE), q1 = (int)(v0.y * QSCALE);
    int q2 = (int)(v0.z * QSCALE), q3 = (int)(v0.w * QSCALE);
    int q4 = (int)(v1.x * QSCALE), q5 = (int)(v1.y * QSCALE);
    int q6 = (int)(v1.z * QSCALE), q7 = (int)(v1.w * QSCALE);
    swq[rb + 0] = q0; swq[rb + 1] = q1; swq[rb + 2] = q2; swq[rb + 3] = q3;
    swq[rb + 4] = q4; swq[rb + 5] = q5; swq[rb + 6] = q6; swq[rb + 7] = q7;
    int ls = ((q0 + q1) + (q2 + q3)) + ((q4 + q5) + (q6 + q7));
#pragma unroll
    for (int o = 16; o; o >>= 1) ls += __shfl_xor_sync(~0u, ls, o);
    if ((t & 31) == 0) sredi[t >> 5] = ls;
    __syncthreads();
    if (t == 0) {
        int S = 0;
#pragma unroll
        for (int k = 0; k < 16; k++) S += sredi[k];
        float bf = 0.05f * (float)S;
        sboundf = bf;
        sboundi = (int)bf - 4096;  // slack: int test fires <= float crossing
    }
    __syncthreads();
    float bound = sboundf;
    int bound_i = sboundi;

    int w = t >> 5;
    int lane = t & 31;
    int p = (pg << 4) + w;
    int row = p >> 6;
    int col = p & 63;
    int pbase = row * PITCH + col;
    unsigned pb = ((unsigned)row << 8) | (unsigned)col;

    int cum_i = 0;                  // warp-uniform integer running sum
    float cumfL = 0.f;              // per-lane distributed float running sum
    float acc0 = 0.f, acc1 = 0.f;   // per-lane distributed d^2*w accumulators

    const uint4* tp = (const uint4*)g_tab;  // uint4 = 2 entries

    for (int base = 0; base < NPAD; base += 128) {
        uint4 c0 = __ldg(tp + (base >> 1) + lane);        // entries A, B
        uint4 c1 = __ldg(tp + (base >> 1) + 32 + lane);   // entries C, D

        // SWAR validity: S = word0 + pb; valid <=> (S & 0xC0C0) == 0x4040
        unsigned sA = c0.x + pb;
        int iA = ((sA & 0xC0C0u) == 0x4040u) ? pbase + ((int)c0.x >> 16) : ZSLOT;
        int qA = swq[iA];
        float wA = (float)qA, dA = __uint_as_float(c0.y);
        unsigned sB = c0.z + pb;
        int iB = ((sB & 0xC0C0u) == 0x4040u) ? pbase + ((int)c0.z >> 16) : ZSLOT;
        int qB = swq[iB];
        float wB = (float)qB, dB = __uint_as_float(c0.w);
        unsigned sC = c1.x + pb;
        int iC = ((sC & 0xC0C0u) == 0x4040u) ? pbase + ((int)c1.x >> 16) : ZSLOT;
        int qC = swq[iC];
        float wC = (float)qC, dC = __uint_as_float(c1.y);
        unsigned sD = c1.z + pb;
        int iD = ((sD & 0xC0C0u) == 0x4040u) ? pbase + ((int)c1.z >> 16) : ZSLOT;
        int qD = swq[iD];
        float wD = (float)qD, dD = __uint_as_float(c1.w);

        int mi = (qA + qB) + (qC + qD);
        int tot_i = __reduce_add_sync(~0u, mi);   // single-instr warp reduce

        float p0 = wA + wB, p1 = wC + wD;

        if (cum_i + tot_i >= bound_i) {  // warp-uniform, fires <= float cross
            // resolve (rare): reconstruct float cum, ordered scans
            float cumf = cumfL;
#pragma unroll
            for (int o = 1; o < 32; o <<= 1)
                cumf += __shfl_xor_sync(~0u, cumf, o);
            float s0 = p0;
#pragma unroll
            for (int o = 1; o < 32; o <<= 1) {
                float u = __shfl_up_sync(~0u, s0, o);
                if (lane >= o) s0 += u;
            }
            float totA = __shfl_sync(~0u, s0, 31);
            float s1 = p1;
#pragma unroll
            for (int o = 1; o < 32; o <<= 1) {
                float u = __shfl_up_sync(~0u, s1, o);
                if (lane >= o) s1 += u;
            }
            float bA = cumf + (s0 - p0);          // weight before entry A
            float bC = cumf + totA + (s1 - p1);   // weight before entry C
            bool fA = bA + wA >= bound;
            bool fB = bA + wA + wB >= bound;
            bool fC = bC + wC >= bound;
            bool fD = bC + wC + wD >= bound;
            unsigned mAB = __ballot_sync(~0u, fA | fB);
            unsigned mCD = __ballot_sync(~0u, fC | fD);
            int crossed = 0;
            if (mAB) {
                int fl = __ffs(mAB) - 1;
                if (lane < fl) acc0 += dA * wA + dB * wB;
                else if (lane == fl)
                    acc0 += fA ? dA * (bound - bA)
                               : dA * wA + dB * (bound - (bA + wA));
                crossed = 1;
            } else if (mCD) {
                int fl = __ffs(mCD) - 1;
                acc0 += dA * wA + dB * wB;  // all of segment A precedes
                if (lane < fl) acc1 += dC * wC + dD * wD;
                else if (lane == fl)
                    acc1 += fC ? dC * (bound - bC)
                               : dC * wC + dD * (bound - (bC + wC));
                crossed = 1;
            }
            if (crossed) break;  // warp-uniform exit
            // int fired early (slack/rounding) — keep scanning
        }
        cum_i += tot_i;
        cumfL += p0 + p1;
        acc0 += dA * wA + dB * wB;
        acc1 += dC * wC + dD * wD;
    }

    float accL = acc0 + acc1;
#pragma unroll
    for (int o = 16; o; o >>= 1) accL += __shfl_xor_sync(~0u, accL, o);
    if (lane == 0) out[slice * HW + p] = sqrtf(accL / bound);
}

extern "C" void kernel_launch(void* const* d_in, const int* in_sizes, int n_in,
                              void* d_out, int out_size) {
    const float* x = (const float*)d_in[0];
    float* out = (float*)d_out;

    k_build<<<(NPAD * 8) / 256, 256>>>();
    k_main<<<NSLICE * 256, 512>>>(x, out);
}

// round 11
// speedup vs baseline: 2.0299x; 1.3560x over previous
#include <cuda_runtime.h>

// DTM (distance-to-measure) on a 64x64 integer grid.
// Per (b,c) slice: bound = 0.05 * sum(w). Per point p: walk grid points in
// order of increasing squared distance, accumulate weight until crossing
// bound, output sqrt((sum_{d<d*} d^2 w + d*^2 (bound - cum_before)) / bound).
// Weights quantized to q = floor(w * 65535): we solve that perturbed problem
// (result is scale-invariant in w, so rel err ~1e-5 << 1e-3). Crossing index
// is computed EXACTLY in integers (REDUX + int scans); the value uses float
// images of the exact ints (q <= 65535 is float-exact).
//
// Gather: weights in a guard-padded u16 array (pitch 127, rows -63..126,
// 63-entry front guard). idx = pbase + (dy*127+dx) hits the real cell when
// in bounds and a provably-zero pad cell otherwise (cols 64..126 absorb dx
// over/underflow, guard rows absorb dy). No validity test in the loop.
//
// Batch entry order: lane l holds entries {2l,2l+1} (seg AB = 0..63) and
// {64+2l,64+2l+1} (seg CD). Resolve scans the two segments separately.

#define HW 4096
#define NSLICE 12
#define NOFF 16129            // (dy,dx) in [-63,63]^2
#define NPAD 16256            // multiple of 128 (127 batches)
#define PITCH 127
#define GUARD 63
#define SMU16 24256           // 63 + 190*127 = 24193 used; rounded up
#define PADOFF 8065u          // pad-entry offset: always hits a zero cell

// entry: .x = (int)(dy*127+dx) bits;  .y = float(d2) bits
__device__ __align__(16) uint2 g_tab[NPAD];

// ---- build: 8 lanes per offset compute its sorted rank in closed form ----

__global__ void __launch_bounds__(256) k_build() {
    int gid = blockIdx.x * 256 + threadIdx.x;  // gid < 8*NPAD
    int i = gid >> 3;
    int q = gid & 7;
    int dy = i / 127 - 63;
    int dx = i % 127 - 63;
    int d2 = dy * dy + dx * dx;
    int pos = 0;
    if (i < NOFF) {
        for (int a = q; a <= 63; a += 8) {  // +-a handled together
            int na = d2 - a * a;
            if (na < 0) break;
            int s = (int)sqrtf((float)na);  // exact floor at these magnitudes
            bool perf = (s * s == na);
            if (na > 0) {                   // # of b with b^2 < na, |b|<=63
                int tt = perf ? s - 1 : s;
                if (tt > 63) tt = 63;
                int cb = 2 * tt + 1;
                pos += (a == 0) ? cb : 2 * cb;
            }
            if (perf && s <= 63) {          // ties b = +-s, lex (a,b) order
                if (a < dy) pos += (s == 0) ? 1 : 2;
                else if (a == dy) {
                    if (-s < dx) pos++;
                    if (s != 0 && s < dx) pos++;
                }
                if (a != 0) {
                    int aa = -a;
                    if (aa < dy) pos += (s == 0) ? 1 : 2;
                    else if (aa == dy) {
                        if (-s < dx) pos++;
                        if (s != 0 && s < dx) pos++;
                    }
                }
            }
        }
    }
    pos += __shfl_xor_sync(~0u, pos, 1);
    pos += __shfl_xor_sync(~0u, pos, 2);
    pos += __shfl_xor_sync(~0u, pos, 4);
    if (q == 0) {
        if (i >= NOFF) {
            if (i < NPAD) g_tab[i] = make_uint2(PADOFF, 0u);  // zero cell
        } else {
            g_tab[pos] = make_uint2((unsigned)(dy * PITCH + dx),
                                    __float_as_uint((float)d2));
        }
    }
}

// ---- main: one warp per point, 128 sorted entries per step (4/lane) ----

__global__ void __launch_bounds__(512, 4)
k_main(const float* __restrict__ x, float* __restrict__ out) {
    __shared__ unsigned short swq[SMU16];  // guard-padded quantized weights
    __shared__ int sredi[16];
    __shared__ int sS;

    int t = threadIdx.x;
    int slice = blockIdx.x >> 8;   // 256 point-groups of 16 per slice
    int pg = blockIdx.x & 255;
    const float4* src4 = (const float4*)(x + slice * HW);

    // zero everything (u32 writes), then place data
    unsigned* z32 = (unsigned*)swq;
    for (int i = t; i < SMU16 / 2; i += 512) z32[i] = 0;
    __syncthreads();

    // 8 contiguous cells per thread (never crosses a row)
    float4 v0 = src4[t * 2];
    float4 v1 = src4[t * 2 + 1];
    int cell = t * 8;
    int rb = GUARD + ((cell >> 6) + 63) * PITCH + (cell & 63);
    int q0 = (int)(v0.x * 65535.0f), q1 = (int)(v0.y * 65535.0f);
    int q2 = (int)(v0.z * 65535.0f), q3 = (int)(v0.w * 65535.0f);
    int q4 = (int)(v1.x * 65535.0f), q5 = (int)(v1.y * 65535.0f);
    int q6 = (int)(v1.z * 65535.0f), q7 = (int)(v1.w * 65535.0f);
    swq[rb + 0] = (unsigned short)q0; swq[rb + 1] = (unsigned short)q1;
    swq[rb + 2] = (unsigned short)q2; swq[rb + 3] = (unsigned short)q3;
    swq[rb + 4] = (unsigned short)q4; swq[rb + 5] = (unsigned short)q5;
    swq[rb + 6] = (unsigned short)q6; swq[rb + 7] = (unsigned short)q7;
    int ls = ((q0 + q1) + (q2 + q3)) + ((q4 + q5) + (q6 + q7));
#pragma unroll
    for (int o = 16; o; o >>= 1) ls += __shfl_xor_sync(~0u, ls, o);
    if ((t & 31) == 0) sredi[t >> 5] = ls;
    __syncthreads();
    if (t == 0) {
        int S = 0;
#pragma unroll
        for (int k = 0; k < 16; k++) S += sredi[k];
        sS = S;
    }
    __syncthreads();
    int S = sS;
    int Bc = (S + 19) / 20;            // first exact int cum >= Bc crosses
    float boundf = 0.05f * (float)S;   // value-space bound (q units)

    int w = t >> 5;
    int lane = t & 31;
    int p = (pg << 4) + w;
    int row = p >> 6;
    int col = p & 63;
    int pbase = GUARD + (row + 63) * PITCH + col;

    int cum = 0;                    // warp-uniform exact int running sum
    float acc0 = 0.f, acc1 = 0.f;   // per-lane distributed d2*q accumulators

    const uint4* tp = (const uint4*)g_tab;  // uint4 = 2 entries

    for (int base = 0; base < NPAD; base += 128) {
        uint4 c0 = __ldg(tp + (base >> 1) + lane);        // entries A, B
        uint4 c1 = __ldg(tp + (base >> 1) + 32 + lane);   // entries C, D

        int qA = swq[pbase + (int)c0.x];
        int qB = swq[pbase + (int)c0.z];
        int qC = swq[pbase + (int)c1.x];
        int qD = swq[pbase + (int)c1.z];
        float dA = __uint_as_float(c0.y), dB = __uint_as_float(c0.w);
        float dC = __uint_as_float(c1.y), dD = __uint_as_float(c1.w);

        int pAB = qA + qB, pCD = qC + qD;
        int tot = __reduce_add_sync(~0u, pAB + pCD);  // uniform across lanes

        if (cum + tot >= Bc) {  // exact: crossing is inside this batch
            // two-segment ordered resolve: seg AB (entries 0..63 of batch)
            // precedes seg CD (entries 64..127)
            int s0 = pAB;
#pragma unroll
            for (int o = 1; o < 32; o <<= 1) {
                int u = __shfl_up_sync(~0u, s0, o);
                if (lane >= o) s0 += u;
            }
            int totAB = __shfl_sync(~0u, s0, 31);
            int s1 = pCD;
#pragma unroll
            for (int o = 1; o < 32; o <<= 1) {
                int u = __shfl_up_sync(~0u, s1, o);
                if (lane >= o) s1 += u;
            }
            int bA = cum + s0 - pAB;           // cum before this lane's A
            int bC = cum + totAB + s1 - pCD;   // cum before this lane's C
            int eA1 = bA + qA, eA2 = eA1 + qB;
            int eC1 = bC + qC, eC2 = eC1 + qD;
            unsigned mAB = __ballot_sync(~0u, eA2 >= Bc);
            unsigned mCD = __ballot_sync(~0u, eC2 >= Bc);  // bit31 set if !mAB
            if (mAB) {
                int fl = __ffs(mAB) - 1;
                if (lane < fl) {
                    acc0 += dA * (float)qA + dB * (float)qB;
                } else if (lane == fl) {
                    if (eA1 >= Bc)
                        acc0 += dA * (boundf - (float)bA);
                    else
                        acc0 += dA * (float)qA + dB * (boundf - (float)eA1);
                }
                // no lane contributes CD (all after crossing)
            } else {
                int fl = __ffs(mCD) - 1;
                acc0 += dA * (float)qA + dB * (float)qB;  // all AB precede
                if (lane < fl) {
                    acc1 += dC * (float)qC + dD * (float)qD;
                } else if (lane == fl) {
                    if (eC1 >= Bc)
                        acc1 += dC * (boundf - (float)bC);
                    else
                        acc1 += dC * (float)qC + dD * (boundf - (float)eC1);
                }
            }
            break;  // warp-uniform exit
        }
        cum += tot;
        acc0 += dA * (float)qA + dB * (float)qB;
        acc1 += dC * (float)qC + dD * (float)qD;
    }

    float accL = acc0 + acc1;
#pragma unroll
    for (int o = 16; o; o >>= 1) accL += __shfl_xor_sync(~0u, accL, o);
    if (lane == 0) out[slice * HW + p] = sqrtf(accL / boundf);
}

extern "C" void kernel_launch(void* const* d_in, const int* in_sizes, int n_in,
                              void* d_out, int out_size) {
    const float* x = (const float*)d_in[0];
    float* out = (float*)d_out;

    k_build<<<(NPAD * 8) / 256, 256>>>();
    k_main<<<NSLICE * 256, 512>>>(x, out);
}

// round 12
// speedup vs baseline: 2.2961x; 1.1311x over previous
#include <cuda_runtime.h>

// DTM (distance-to-measure) on a 64x64 integer grid.
// Per (b,c) slice: bound = 0.05 * sum(w). Per point p: walk grid points in
// order of increasing squared distance, accumulate weight until crossing
// bound, output sqrt((sum_{d<d*} d^2 w + d*^2 (bound - cum_before)) / bound).
// Weights quantized to q = floor(w * 65535): we solve that perturbed problem
// (result is scale-invariant in w, so rel err ~1e-5 << 1e-3). Crossing index
// is computed EXACTLY in integers (REDUX + int scans); the value uses float
// images of the exact ints (q <= 65535 is float-exact).
//
// Gather: weights in a guard-padded u16 array (pitch 127, rows -63..126,
// 63-entry front guard). idx = pbase + (dy*127+dx) hits the real cell when
// in bounds and a provably-zero pad cell otherwise. No validity test.
//
// Blocks are persistent per slice chunk: one prologue (zero + load + reduce)
// serves ~5.3 point-groups per block; warps walk their points independently
// with no further synchronization (smem is read-only after the barrier).

#define HW 4096
#define NSLICE 12
#define NOFF 16129            // (dy,dx) in [-63,63]^2
#define NPAD 16256            // multiple of 128 (127 batches)
#define PITCH 127
#define GUARD 63
#define SMU16 24256           // 63 + 190*127 = 24193 used; rounded up
#define PADOFF 8065u          // pad-entry offset: always hits a zero cell
#define GPB 48                // blocks per slice (group stride)

// entry: .x = (int)(dy*127+dx) bits;  .y = float(d2) bits
__device__ __align__(16) uint2 g_tab[NPAD];

// ---- build: 8 lanes per offset compute its sorted rank in closed form ----

__global__ void __launch_bounds__(256) k_build() {
    int gid = blockIdx.x * 256 + threadIdx.x;  // gid < 8*NPAD
    int i = gid >> 3;
    int q = gid & 7;
    int dy = i / 127 - 63;
    int dx = i % 127 - 63;
    int d2 = dy * dy + dx * dx;
    int pos = 0;
    if (i < NOFF) {
        for (int a = q; a <= 63; a += 8) {  // +-a handled together
            int na = d2 - a * a;
            if (na < 0) break;
            int s = (int)sqrtf((float)na);  // exact floor at these magnitudes
            bool perf = (s * s == na);
            if (na > 0) {                   // # of b with b^2 < na, |b|<=63
                int tt = perf ? s - 1 : s;
                if (tt > 63) tt = 63;
                int cb = 2 * tt + 1;
                pos += (a == 0) ? cb : 2 * cb;
            }
            if (perf && s <= 63) {          // ties b = +-s, lex (a,b) order
                if (a < dy) pos += (s == 0) ? 1 : 2;
                else if (a == dy) {
                    if (-s < dx) pos++;
                    if (s != 0 && s < dx) pos++;
                }
                if (a != 0) {
                    int aa = -a;
                    if (aa < dy) pos += (s == 0) ? 1 : 2;
                    else if (aa == dy) {
                        if (-s < dx) pos++;
                        if (s != 0 && s < dx) pos++;
                    }
                }
            }
        }
    }
    pos += __shfl_xor_sync(~0u, pos, 1);
    pos += __shfl_xor_sync(~0u, pos, 2);
    pos += __shfl_xor_sync(~0u, pos, 4);
    if (q == 0) {
        if (i >= NOFF) {
            if (i < NPAD) g_tab[i] = make_uint2(PADOFF, 0u);  // zero cell
        } else {
            g_tab[pos] = make_uint2((unsigned)(dy * PITCH + dx),
                                    __float_as_uint((float)d2));
        }
    }
}

// ---- main: warp per point, ~5.3 points per warp, 128 entries per step ----

__global__ void __launch_bounds__(512, 4)
k_main(const float* __restrict__ x, float* __restrict__ out) {
    __shared__ unsigned short swq[SMU16];  // guard-padded quantized weights
    __shared__ int sredi[16];
    __shared__ int sS;

    int t = threadIdx.x;
    int slice = blockIdx.x / GPB;
    int r = blockIdx.x % GPB;      // this block's group residue
    const float4* src4 = (const float4*)(x + slice * HW);

    // zero everything (u32 writes), then place data
    unsigned* z32 = (unsigned*)swq;
    for (int i = t; i < SMU16 / 2; i += 512) z32[i] = 0;
    __syncthreads();

    // 8 contiguous cells per thread (never crosses a row)
    float4 v0 = src4[t * 2];
    float4 v1 = src4[t * 2 + 1];
    int cell = t * 8;
    int rb = GUARD + ((cell >> 6) + 63) * PITCH + (cell & 63);
    int q0 = (int)(v0.x * 65535.0f), q1 = (int)(v0.y * 65535.0f);
    int q2 = (int)(v0.z * 65535.0f), q3 = (int)(v0.w * 65535.0f);
    int q4 = (int)(v1.x * 65535.0f), q5 = (int)(v1.y * 65535.0f);
    int q6 = (int)(v1.z * 65535.0f), q7 = (int)(v1.w * 65535.0f);
    swq[rb + 0] = (unsigned short)q0; swq[rb + 1] = (unsigned short)q1;
    swq[rb + 2] = (unsigned short)q2; swq[rb + 3] = (unsigned short)q3;
    swq[rb + 4] = (unsigned short)q4; swq[rb + 5] = (unsigned short)q5;
    swq[rb + 6] = (unsigned short)q6; swq[rb + 7] = (unsigned short)q7;
    int ls = ((q0 + q1) + (q2 + q3)) + ((q4 + q5) + (q6 + q7));
#pragma unroll
    for (int o = 16; o; o >>= 1) ls += __shfl_xor_sync(~0u, ls, o);
    if ((t & 31) == 0) sredi[t >> 5] = ls;
    __syncthreads();
    if (t == 0) {
        int S = 0;
#pragma unroll
        for (int k = 0; k < 16; k++) S += sredi[k];
        sS = S;
    }
    __syncthreads();
    int S = sS;
    int Bc = (S + 19) / 20;            // first exact int cum >= Bc crosses
    float boundf = 0.05f * (float)S;   // value-space bound (q units)

    int w = t >> 5;
    int lane = t & 31;
    const uint4* tp = (const uint4*)g_tab;  // uint4 = 2 entries
    float* dst = out + slice * HW;

    // each warp walks groups r, r+GPB, ... independently (no syncs needed)
    for (int g = r; g < 256; g += GPB) {
        int p = (g << 4) + w;
        int row = p >> 6;
        int col = p & 63;
        int pbase = GUARD + (row + 63) * PITCH + col;

        int cum = 0;                    // warp-uniform exact int running sum
        float acc0 = 0.f, acc1 = 0.f;   // distributed d2*q accumulators

        for (int base = 0; base < NPAD; base += 128) {
            uint4 c0 = __ldg(tp + (base >> 1) + lane);       // entries A, B
            uint4 c1 = __ldg(tp + (base >> 1) + 32 + lane);  // entries C, D

            int qA = swq[pbase + (int)c0.x];
            int qB = swq[pbase + (int)c0.z];
            int qC = swq[pbase + (int)c1.x];
            int qD = swq[pbase + (int)c1.z];
            float dA = __uint_as_float(c0.y), dB = __uint_as_float(c0.w);
            float dC = __uint_as_float(c1.y), dD = __uint_as_float(c1.w);

            int pAB = qA + qB, pCD = qC + qD;
            int tot = __reduce_add_sync(~0u, pAB + pCD);  // uniform

            if (cum + tot >= Bc) {  // exact: crossing inside this batch
                // two-segment ordered resolve: seg AB (entries 0..63)
                // precedes seg CD (entries 64..127)
                int s0 = pAB;
#pragma unroll
                for (int o = 1; o < 32; o <<= 1) {
                    int u = __shfl_up_sync(~0u, s0, o);
                    if (lane >= o) s0 += u;
                }
                int totAB = __shfl_sync(~0u, s0, 31);
                int s1 = pCD;
#pragma unroll
                for (int o = 1; o < 32; o <<= 1) {
                    int u = __shfl_up_sync(~0u, s1, o);
                    if (lane >= o) s1 += u;
                }
                int bA = cum + s0 - pAB;          // cum before lane's A
                int bC = cum + totAB + s1 - pCD;  // cum before lane's C
                int eA1 = bA + qA, eA2 = eA1 + qB;
                int eC1 = bC + qC, eC2 = eC1 + qD;
                unsigned mAB = __ballot_sync(~0u, eA2 >= Bc);
                unsigned mCD = __ballot_sync(~0u, eC2 >= Bc);  // b31 if !mAB
                if (mAB) {
                    int fl = __ffs(mAB) - 1;
                    if (lane < fl) {
                        acc0 += dA * (float)qA + dB * (float)qB;
                    } else if (lane == fl) {
                        if (eA1 >= Bc)
                            acc0 += dA * (boundf - (float)bA);
                        else
                            acc0 += dA * (float)qA + dB * (boundf - (float)eA1);
                    }
                } else {
                    int fl = __ffs(mCD) - 1;
                    acc0 += dA * (float)qA + dB * (float)qB;  // all AB precede
                    if (lane < fl) {
                        acc1 += dC * (float)qC + dD * (float)qD;
                    } else if (lane == fl) {
                        if (eC1 >= Bc)
                            acc1 += dC * (boundf - (float)bC);
                        else
                            acc1 += dC * (float)qC + dD * (boundf - (float)eC1);
                    }
                }
                break;  // warp-uniform exit
            }
            cum += tot;
            acc0 += dA * (float)qA + dB * (float)qB;
            acc1 += dC * (float)qC + dD * (float)qD;
        }

        float accL = acc0 + acc1;
#pragma unroll
        for (int o = 16; o; o >>= 1) accL += __shfl_xor_sync(~0u, accL, o);
        if (lane == 0) dst[p] = sqrtf(accL / boundf);
    }
}

extern "C" void kernel_launch(void* const* d_in, const int* in_sizes, int n_in,
                              void* d_out, int out_size) {
    const float* x = (const float*)d_in[0];
    float* out = (float*)d_out;

    k_build<<<(NPAD * 8) / 256, 256>>>();
    k_main<<<NSLICE * GPB, 512>>>(x, out);
}

// round 13
// speedup vs baseline: 2.2985x; 1.0010x over previous
#include <cuda_runtime.h>

// DTM (distance-to-measure) on a 64x64 integer grid.
// Per (b,c) slice: bound = 0.05 * sum(w). Per point p: walk grid points in
// order of increasing squared distance, accumulate weight until crossing
// bound, output sqrt((sum_{d<d*} d^2 w + d*^2 (bound - cum_before)) / bound).
// Weights quantized to q = floor(w * 65535): we solve that perturbed problem
// (result is scale-invariant in w, so rel err ~1e-5 << 1e-3). Crossing index
// is computed EXACTLY in integers (REDUX + int scan); the value accumulates
// exact u32 batch sums of d2*q (<= 2.08e9, fits u32), one I2F per batch.
//
// Gather: weights in a guard-padded u16 array (pitch 127, rows -63..126,
// 63-entry front guard). idx = pbase2 + (off+8064) hits the real cell when
// in bounds and a provably-zero pad cell otherwise. No validity test.
// Pad table entries use biased offset 16129: for all pbase2 in [0,8064],
// idx lands in row-126 cols>=64 / guard rows / zeroed tail — always zero.
//
// Table entry (u32): d2 << 14 | (dy*127+dx + 8064).  Lane l owns entries
// 4l..4l+3 of each 128-entry batch (contiguous => single-scan resolve).

#define HW 4096
#define NSLICE 12
#define NOFF 16129            // (dy,dx) in [-63,63]^2
#define NPAD 16256            // multiple of 128 (127 batches)
#define PITCH 127
#define GUARD 63
#define SMU16 24256           // 63 + 190*127 = 24193 used; rounded up
#define PADENT 16129u         // pad entry: d2=0, off lands in zero cells
#define GPB 48                // blocks per slice (group stride)

__device__ __align__(16) unsigned g_tab[NPAD];

// ---- build: 8 lanes per offset compute its sorted rank in closed form ----

__global__ void __launch_bounds__(256) k_build() {
    int gid = blockIdx.x * 256 + threadIdx.x;  // gid < 8*NPAD
    int i = gid >> 3;
    int q = gid & 7;
    int dy = i / 127 - 63;
    int dx = i % 127 - 63;
    int d2 = dy * dy + dx * dx;
    int pos = 0;
    if (i < NOFF) {
        for (int a = q; a <= 63; a += 8) {  // +-a handled together
            int na = d2 - a * a;
            if (na < 0) break;
            int s = (int)sqrtf((float)na);  // exact floor at these magnitudes
            bool perf = (s * s == na);
            if (na > 0) {                   // # of b with b^2 < na, |b|<=63
                int tt = perf ? s - 1 : s;
                if (tt > 63) tt = 63;
                int cb = 2 * tt + 1;
                pos += (a == 0) ? cb : 2 * cb;
            }
            if (perf && s <= 63) {          // ties b = +-s, lex (a,b) order
                if (a < dy) pos += (s == 0) ? 1 : 2;
                else if (a == dy) {
                    if (-s < dx) pos++;
                    if (s != 0 && s < dx) pos++;
                }
                if (a != 0) {
                    int aa = -a;
                    if (aa < dy) pos += (s == 0) ? 1 : 2;
                    else if (aa == dy) {
                        if (-s < dx) pos++;
                        if (s != 0 && s < dx) pos++;
                    }
                }
            }
        }
    }
    pos += __shfl_xor_sync(~0u, pos, 1);
    pos += __shfl_xor_sync(~0u, pos, 2);
    pos += __shfl_xor_sync(~0u, pos, 4);
    if (q == 0) {
        if (i >= NOFF) {
            g_tab[i] = PADENT;  // i < NPAD by grid sizing
        } else {
            g_tab[pos] = ((unsigned)d2 << 14) |
                         (unsigned)(dy * PITCH + dx + 8064);
        }
    }
}

// ---- main: warp per point, ~5.3 points per warp, 128 entries per step ----

__global__ void __launch_bounds__(512, 4)
k_main(const float* __restrict__ x, float* __restrict__ out) {
    __shared__ unsigned short swq[SMU16];  // guard-padded quantized weights
    __shared__ int sredi[16];
    __shared__ int sS;

    int t = threadIdx.x;
    int slice = blockIdx.x / GPB;
    int r = blockIdx.x % GPB;      // this block's group residue
    const float4* src4 = (const float4*)(x + slice * HW);

    // zero everything (u32 writes), then place data
    unsigned* z32 = (unsigned*)swq;
    for (int i = t; i < SMU16 / 2; i += 512) z32[i] = 0;
    __syncthreads();

    // 8 contiguous cells per thread (never crosses a row)
    float4 v0 = src4[t * 2];
    float4 v1 = src4[t * 2 + 1];
    int cell = t * 8;
    int rb = GUARD + ((cell >> 6) + 63) * PITCH + (cell & 63);
    int q0 = (int)(v0.x * 65535.0f), q1 = (int)(v0.y * 65535.0f);
    int q2 = (int)(v0.z * 65535.0f), q3 = (int)(v0.w * 65535.0f);
    int q4 = (int)(v1.x * 65535.0f), q5 = (int)(v1.y * 65535.0f);
    int q6 = (int)(v1.z * 65535.0f), q7 = (int)(v1.w * 65535.0f);
    swq[rb + 0] = (unsigned short)q0; swq[rb + 1] = (unsigned short)q1;
    swq[rb + 2] = (unsigned short)q2; swq[rb + 3] = (unsigned short)q3;
    swq[rb + 4] = (unsigned short)q4; swq[rb + 5] = (unsigned short)q5;
    swq[rb + 6] = (unsigned short)q6; swq[rb + 7] = (unsigned short)q7;
    int ls = ((q0 + q1) + (q2 + q3)) + ((q4 + q5) + (q6 + q7));
#pragma unroll
    for (int o = 16; o; o >>= 1) ls += __shfl_xor_sync(~0u, ls, o);
    if ((t & 31) == 0) sredi[t >> 5] = ls;
    __syncthreads();
    if (t == 0) {
        int S = 0;
#pragma unroll
        for (int k = 0; k < 16; k++) S += sredi[k];
        sS = S;
    }
    __syncthreads();
    int S = sS;
    int Bc = (S + 19) / 20;            // first exact int cum >= Bc crosses
    float boundf = 0.05f * (float)S;   // value-space bound (q units)

    int w = t >> 5;
    int lane = t & 31;
    const uint4* tp = (const uint4*)g_tab;  // uint4 = 4 packed entries
    float* dst = out + slice * HW;

    // each warp walks groups r, r+GPB, ... independently (no syncs needed)
    for (int g = r; g < 256; g += GPB) {
        int p = (g << 4) + w;
        int row = p >> 6;
        int col = p & 63;
        int pbase2 = GUARD + (row + 63) * PITCH + col - 8064;

        int cum = 0;       // warp-uniform exact int running sum
        float accf = 0.f;  // per-lane distributed value accumulator

        uint4 c = __ldg(tp + lane);  // prefetched batch (entries 4l..4l+3)

        for (int base = 0; base < NPAD; base += 128) {
            int nb = (base >> 2) + 32 + lane;
            uint4 nx = (base + 128 < NPAD) ? __ldg(tp + nb) : c;

            int qA = swq[pbase2 + (int)(c.x & 0x3FFFu)];
            int qB = swq[pbase2 + (int)(c.y & 0x3FFFu)];
            int qC = swq[pbase2 + (int)(c.z & 0x3FFFu)];
            int qD = swq[pbase2 + (int)(c.w & 0x3FFFu)];
            unsigned dA = c.x >> 14, dB = c.y >> 14;
            unsigned dC = c.z >> 14, dD = c.w >> 14;

            int mi = (qA + qB) + (qC + qD);
            int tot = __reduce_add_sync(~0u, mi);  // uniform across lanes
            // exact u32 batch sum of d2*q (<= 4*7938*65535 < 2^32)
            unsigned bsum = dA * (unsigned)qA + dB * (unsigned)qB +
                            dC * (unsigned)qC + dD * (unsigned)qD;

            if (cum + tot >= Bc) {  // exact: crossing inside this batch
                // single-scan resolve: lane l's entries 4l..4l+3 contiguous
                int s = mi;
#pragma unroll
                for (int o = 1; o < 32; o <<= 1) {
                    int u = __shfl_up_sync(~0u, s, o);
                    if (lane >= o) s += u;
                }
                int b0 = cum + s - mi;  // exact cum before lane's entries
                int e1 = b0 + qA, e2 = e1 + qB, e3 = e2 + qC, e4 = e3 + qD;
                unsigned m = __ballot_sync(~0u, e4 >= Bc);  // bit31 set
                int fl = __ffs(m) - 1;
                if (lane < fl) {
                    accf += (float)bsum;
                } else if (lane == fl) {
                    float fA = (float)(int)dA, fB = (float)(int)dB;
                    float fC = (float)(int)dC, fD = (float)(int)dD;
                    if (e1 >= Bc) {
                        accf += fA * (boundf - (float)b0);
                    } else {
                        accf += fA * (float)qA;
                        if (e2 >= Bc) {
                            accf += fB * (boundf - (float)e1);
                        } else {
                            accf += fB * (float)qB;
                            if (e3 >= Bc) {
                                accf += fC * (boundf - (float)e2);
                            } else {
                                accf += fC * (float)qC;
                                accf += fD * (boundf - (float)e3);
                            }
                        }
                    }
                }
                break;  // warp-uniform exit (crossing guaranteed: S >= Bc)
            }
            cum += tot;
            accf += (float)bsum;
            c = nx;
        }

#pragma unroll
        for (int o = 16; o; o >>= 1) accf += __shfl_xor_sync(~0u, accf, o);
        if (lane == 0) dst[p] = sqrtf(accf / boundf);
    }
}

extern "C" void kernel_launch(void* const* d_in, const int* in_sizes, int n_in,
                              void* d_out, int out_size) {
    const float* x = (const float*)d_in[0];
    float* out = (float*)d_out;

    k_build<<<(NPAD * 8) / 256, 256>>>();
    k_main<<<NSLICE * GPB, 512>>>(x, out);
}

// round 14
// speedup vs baseline: 2.4359x; 1.0598x over previous
#include <cuda_runtime.h>

// DTM (distance-to-measure) on a 64x64 integer grid.
// Per (b,c) slice: bound = 0.05 * sum(w). Per point p: walk grid points in
// order of increasing squared distance, accumulate weight until crossing
// bound, output sqrt((sum_{d<d*} d^2 w + d*^2 (bound - cum_before)) / bound).
// Weights quantized to q = floor(w * 65535): we solve that perturbed problem
// (result is scale-invariant in w, so rel err ~1e-5 << 1e-3). Crossing index
// is computed EXACTLY in integers (one REDUX per 256 entries + int scans);
// the value accumulates exact u32 segment sums of d2*q, one I2F per segment.
//
// Gather: weights in a guard-padded u16 array (pitch 127, rows -63..126,
// 63-entry front guard). idx = pbase2 + (off+8064) hits the real cell when
// in bounds and a provably-zero pad cell otherwise. No validity test.
//
// Table entry (u32): d2 << 14 | (dy*127+dx + 8064). Super-batch = 256
// entries: lane l owns entries {4l..4l+3} (seg0) and {128+4l..} (seg1);
// within each segment a lane's 4 entries are contiguous in sorted order,
// so the resolve is segment-select + single scan.

#define HW 4096
#define NSLICE 12
#define NOFF 16129            // (dy,dx) in [-63,63]^2
#define NPAD 16384            // multiple of 256 (64 super-batches)
#define PITCH 127
#define GUARD 63
#define SMU16 24256           // 63 + 190*127 = 24193 used; rounded up
#define PADENT 16129u         // pad entry: d2=0, off lands in zero cells
#define GPB 48                // blocks per slice (group stride)

__device__ __align__(16) unsigned g_tab[NPAD];

// ---- build: 8 lanes per offset compute its sorted rank in closed form ----

__global__ void __launch_bounds__(256) k_build() {
    int gid = blockIdx.x * 256 + threadIdx.x;  // gid < 8*NPAD
    int i = gid >> 3;
    int q = gid & 7;
    int dy = i / 127 - 63;
    int dx = i % 127 - 63;
    int d2 = dy * dy + dx * dx;
    int pos = 0;
    if (i < NOFF) {
        for (int a = q; a <= 63; a += 8) {  // +-a handled together
            int na = d2 - a * a;
            if (na < 0) break;
            int s = (int)sqrtf((float)na);  // exact floor at these magnitudes
            bool perf = (s * s == na);
            if (na > 0) {                   // # of b with b^2 < na, |b|<=63
                int tt = perf ? s - 1 : s;
                if (tt > 63) tt = 63;
                int cb = 2 * tt + 1;
                pos += (a == 0) ? cb : 2 * cb;
            }
            if (perf && s <= 63) {          // ties b = +-s, lex (a,b) order
                if (a < dy) pos += (s == 0) ? 1 : 2;
                else if (a == dy) {
                    if (-s < dx) pos++;
                    if (s != 0 && s < dx) pos++;
                }
                if (a != 0) {
                    int aa = -a;
                    if (aa < dy) pos += (s == 0) ? 1 : 2;
                    else if (aa == dy) {
                        if (-s < dx) pos++;
                        if (s != 0 && s < dx) pos++;
                    }
                }
            }
        }
    }
    pos += __shfl_xor_sync(~0u, pos, 1);
    pos += __shfl_xor_sync(~0u, pos, 2);
    pos += __shfl_xor_sync(~0u, pos, 4);
    if (q == 0) {
        if (i >= NOFF) {
            g_tab[i] = PADENT;  // i < NPAD by grid sizing
        } else {
            g_tab[pos] = ((unsigned)d2 << 14) |
                         (unsigned)(dy * PITCH + dx + 8064);
        }
    }
}

// ---- main: warp per point, ~5.3 points per warp, 256 entries per step ----

__global__ void __launch_bounds__(512, 4)
k_main(const float* __restrict__ x, float* __restrict__ out) {
    __shared__ unsigned short swq[SMU16];  // guard-padded quantized weights
    __shared__ int sredi[16];
    __shared__ int sS;

    int t = threadIdx.x;
    int slice = blockIdx.x / GPB;
    int r = blockIdx.x % GPB;      // this block's group residue
    const float4* src4 = (const float4*)(x + slice * HW);

    // zero everything (u32 writes), then place data
    unsigned* z32 = (unsigned*)swq;
    for (int i = t; i < SMU16 / 2; i += 512) z32[i] = 0;
    __syncthreads();

    // 8 contiguous cells per thread (never crosses a row)
    float4 v0 = src4[t * 2];
    float4 v1 = src4[t * 2 + 1];
    int cell = t * 8;
    int rb = GUARD + ((cell >> 6) + 63) * PITCH + (cell & 63);
    int q0 = (int)(v0.x * 65535.0f), q1 = (int)(v0.y * 65535.0f);
    int q2 = (int)(v0.z * 65535.0f), q3 = (int)(v0.w * 65535.0f);
    int q4 = (int)(v1.x * 65535.0f), q5 = (int)(v1.y * 65535.0f);
    int q6 = (int)(v1.z * 65535.0f), q7 = (int)(v1.w * 65535.0f);
    swq[rb + 0] = (unsigned short)q0; swq[rb + 1] = (unsigned short)q1;
    swq[rb + 2] = (unsigned short)q2; swq[rb + 3] = (unsigned short)q3;
    swq[rb + 4] = (unsigned short)q4; swq[rb + 5] = (unsigned short)q5;
    swq[rb + 6] = (unsigned short)q6; swq[rb + 7] = (unsigned short)q7;
    int ls = ((q0 + q1) + (q2 + q3)) + ((q4 + q5) + (q6 + q7));
#pragma unroll
    for (int o = 16; o; o >>= 1) ls += __shfl_xor_sync(~0u, ls, o);
    if ((t & 31) == 0) sredi[t >> 5] = ls;
    __syncthreads();
    if (t == 0) {
        int S = 0;
#pragma unroll
        for (int k = 0; k < 16; k++) S += sredi[k];
        sS = S;
    }
    __syncthreads();
    int S = sS;
    int Bc = (S + 19) / 20;            // first exact int cum >= Bc crosses
    float boundf = 0.05f * (float)S;   // value-space bound (q units)

    int w = t >> 5;
    int lane = t & 31;
    const uint4* tp = (const uint4*)g_tab;  // uint4 = 4 packed entries
    float* dst = out + slice * HW;

    // each warp walks groups r, r+GPB, ... independently (no syncs needed)
    for (int g = r; g < 256; g += GPB) {
        int p = (g << 4) + w;
        int row = p >> 6;
        int col = p & 63;
        int pbase2 = GUARD + (row + 63) * PITCH + col - 8064;

        int cum = 0;       // warp-uniform exact int running sum
        float accf = 0.f;  // per-lane distributed value accumulator

        for (int base = 0; base < NPAD; base += 256) {
            uint4 c0 = __ldg(tp + (base >> 2) + lane);       // seg0 entries
            uint4 c1 = __ldg(tp + (base >> 2) + 32 + lane);  // seg1 entries

            int qA = swq[pbase2 + (int)(c0.x & 0x3FFFu)];
            int qB = swq[pbase2 + (int)(c0.y & 0x3FFFu)];
            int qC = swq[pbase2 + (int)(c0.z & 0x3FFFu)];
            int qD = swq[pbase2 + (int)(c0.w & 0x3FFFu)];
            int qE = swq[pbase2 + (int)(c1.x & 0x3FFFu)];
            int qF = swq[pbase2 + (int)(c1.y & 0x3FFFu)];
            int qG = swq[pbase2 + (int)(c1.z & 0x3FFFu)];
            int qH = swq[pbase2 + (int)(c1.w & 0x3FFFu)];

            int mi0 = (qA + qB) + (qC + qD);
            int mi1 = (qE + qF) + (qG + qH);
            int tot = __reduce_add_sync(~0u, mi0 + mi1);  // one per 256

            // exact u32 segment sums of d2*q (<= 4*7938*65535 < 2^32)
            unsigned bs0 = (c0.x >> 14) * (unsigned)qA +
                           (c0.y >> 14) * (unsigned)qB +
                           (c0.z >> 14) * (unsigned)qC +
                           (c0.w >> 14) * (unsigned)qD;
            unsigned bs1 = (c1.x >> 14) * (unsigned)qE +
                           (c1.y >> 14) * (unsigned)qF +
                           (c1.z >> 14) * (unsigned)qG +
                           (c1.w >> 14) * (unsigned)qH;

            if (cum + tot >= Bc) {  // exact: crossing inside these 256
                // segment-select, then single scan (lane's 4 contiguous)
                int s0 = mi0;
#pragma unroll
                for (int o = 1; o < 32; o <<= 1) {
                    int u = __shfl_up_sync(~0u, s0, o);
                    if (lane >= o) s0 += u;
                }
                int tot0 = __shfl_sync(~0u, s0, 31);
                uint4 cc;
                int b0, w0, w1, w2, w3;
                if (cum + tot0 >= Bc) {       // crossing in seg0
                    cc = c0;
                    b0 = cum + s0 - mi0;
                    w0 = qA; w1 = qB; w2 = qC; w3 = qD;
                } else {                      // all of seg0, cross in seg1
                    accf += (float)bs0;
                    int s1 = mi1;
#pragma unroll
                    for (int o = 1; o < 32; o <<= 1) {
                        int u = __shfl_up_sync(~0u, s1, o);
                        if (lane >= o) s1 += u;
                    }
                    cc = c1;
                    b0 = cum + tot0 + s1 - mi1;
                    w0 = qE; w1 = qF; w2 = qG; w3 = qH;
                }
                int e1 = b0 + w0, e2 = e1 + w1, e3 = e2 + w2, e4 = e3 + w3;
                unsigned m = __ballot_sync(~0u, e4 >= Bc);  // bit31 set
                int fl = __ffs(m) - 1;
                if (lane < fl) {
                    // full contribution of this lane's 4 segment entries
                    unsigned bsl = (cc.x >> 14) * (unsigned)w0 +
                                   (cc.y >> 14) * (unsigned)w1 +
                                   (cc.z >> 14) * (unsigned)w2 +
                                   (cc.w >> 14) * (unsigned)w3;
                    accf += (float)bsl;
                } else if (lane == fl) {
                    float fA = (float)(int)(cc.x >> 14);
                    float fB = (float)(int)(cc.y >> 14);
                    float fC = (float)(int)(cc.z >> 14);
                    float fD = (float)(int)(cc.w >> 14);
                    if (e1 >= Bc) {
                        accf += fA * (boundf - (float)b0);
                    } else {
                        accf += fA * (float)w0;
                        if (e2 >= Bc) {
                            accf += fB * (boundf - (float)e1);
                        } else {
                            accf += fB * (float)w1;
                            if (e3 >= Bc) {
                                accf += fC * (boundf - (float)e2);
                            } else {
                                accf += fC * (float)w2;
                                accf += fD * (boundf - (float)e3);
                            }
                        }
                    }
                }
                break;  // warp-uniform exit (crossing guaranteed: S >= Bc)
            }
            cum += tot;
            accf += (float)bs0 + (float)bs1;
        }

#pragma unroll
        for (int o = 16; o; o >>= 1) accf += __shfl_xor_sync(~0u, accf, o);
        if (lane == 0) dst[p] = sqrtf(accf / boundf);
    }
}

extern "C" void kernel_launch(void* const* d_in, const int* in_sizes, int n_in,
                              void* d_out, int out_size) {
    const float* x = (const float*)d_in[0];
    float* out = (float*)d_out;

    k_build<<<(NPAD * 8) / 256, 256>>>();
    k_main<<<NSLICE * GPB, 512>>>(x, out);
}

// round 15
// speedup vs baseline: 2.4572x; 1.0088x over previous
#include <cuda_runtime.h>

// DTM (distance-to-measure) on a 64x64 integer grid.
// Per (b,c) slice: bound = 0.05 * sum(w). Per point p: walk grid points in
// order of increasing squared distance, accumulate weight until crossing
// bound, output sqrt((sum_{d<d*} d^2 w + d*^2 (bound - cum_before)) / bound).
// Weights quantized to q = floor(w * 65535): we solve that perturbed problem
// (result is scale-invariant in w, so rel err ~1e-5 << 1e-3). Crossing index
// is computed EXACTLY in integers (one REDUX per 256 entries + int scans);
// the value accumulates exact u32 segment sums of d2*q, one I2F per segment,
// computed LAZILY (only for non-crossing batches; the resolve recomputes
// just the needed per-lane pieces).
//
// Gather: weights in a guard-padded u16 array (pitch 127, rows -63..126,
// 63-entry front guard). idx = pbase2 + (off+8064) hits the real cell when
// in bounds and a provably-zero pad cell otherwise. No validity test.
//
// Table entry (u32): d2 << 14 | (dy*127+dx + 8064). Super-batch = 256
// entries: lane l owns entries {4l..4l+3} (seg0) and {128+4l..} (seg1);
// within each segment a lane's 4 entries are contiguous in sorted order,
// so the resolve is segment-select + single scan.

#define HW 4096
#define NSLICE 12
#define NOFF 16129            // (dy,dx) in [-63,63]^2
#define NPAD 16384            // multiple of 256 (64 super-batches)
#define PITCH 127
#define GUARD 63
#define SMU16 24256           // 63 + 190*127 = 24193 used; rounded up
#define PADENT 16129u         // pad entry: d2=0, off lands in zero cells
#define GPB 48                // blocks per slice (group stride)

__device__ __align__(16) unsigned g_tab[NPAD];

// ---- build: 8 lanes per offset compute its sorted rank in closed form ----

__global__ void __launch_bounds__(256) k_build() {
    int gid = blockIdx.x * 256 + threadIdx.x;  // gid < 8*NPAD
    int i = gid >> 3;
    int q = gid & 7;
    int dy = i / 127 - 63;
    int dx = i % 127 - 63;
    int d2 = dy * dy + dx * dx;
    int pos = 0;
    if (i < NOFF) {
        for (int a = q; a <= 63; a += 8) {  // +-a handled together
            int na = d2 - a * a;
            if (na < 0) break;
            int s = (int)sqrtf((float)na);  // exact floor at these magnitudes
            bool perf = (s * s == na);
            if (na > 0) {                   // # of b with b^2 < na, |b|<=63
                int tt = perf ? s - 1 : s;
                if (tt > 63) tt = 63;
                int cb = 2 * tt + 1;
                pos += (a == 0) ? cb : 2 * cb;
            }
            if (perf && s <= 63) {          // ties b = +-s, lex (a,b) order
                if (a < dy) pos += (s == 0) ? 1 : 2;
                else if (a == dy) {
                    if (-s < dx) pos++;
                    if (s != 0 && s < dx) pos++;
                }
                if (a != 0) {
                    int aa = -a;
                    if (aa < dy) pos += (s == 0) ? 1 : 2;
                    else if (aa == dy) {
                        if (-s < dx) pos++;
                        if (s != 0 && s < dx) pos++;
                    }
                }
            }
        }
    }
    pos += __shfl_xor_sync(~0u, pos, 1);
    pos += __shfl_xor_sync(~0u, pos, 2);
    pos += __shfl_xor_sync(~0u, pos, 4);
    if (q == 0) {
        if (i >= NOFF) {
            g_tab[i] = PADENT;  // i < NPAD by grid sizing
        } else {
            g_tab[pos] = ((unsigned)d2 << 14) |
                         (unsigned)(dy * PITCH + dx + 8064);
        }
    }
}

// ---- main: warp per point, ~5.3 points per warp, 256 entries per step ----

__global__ void __launch_bounds__(512, 4)
k_main(const float* __restrict__ x, float* __restrict__ out) {
    __shared__ unsigned short swq[SMU16];  // guard-padded quantized weights
    __shared__ int sredi[16];
    __shared__ int sS;

    int t = threadIdx.x;
    int slice = blockIdx.x / GPB;
    int r = blockIdx.x % GPB;      // this block's group residue
    const float4* src4 = (const float4*)(x + slice * HW);

    // zero everything (u32 writes), then place data
    unsigned* z32 = (unsigned*)swq;
    for (int i = t; i < SMU16 / 2; i += 512) z32[i] = 0;
    __syncthreads();

    // 8 contiguous cells per thread (never crosses a row)
    float4 v0 = src4[t * 2];
    float4 v1 = src4[t * 2 + 1];
    int cell = t * 8;
    int rb = GUARD + ((cell >> 6) + 63) * PITCH + (cell & 63);
    int q0 = (int)(v0.x * 65535.0f), q1 = (int)(v0.y * 65535.0f);
    int q2 = (int)(v0.z * 65535.0f), q3 = (int)(v0.w * 65535.0f);
    int q4 = (int)(v1.x * 65535.0f), q5 = (int)(v1.y * 65535.0f);
    int q6 = (int)(v1.z * 65535.0f), q7 = (int)(v1.w * 65535.0f);
    swq[rb + 0] = (unsigned short)q0; swq[rb + 1] = (unsigned short)q1;
    swq[rb + 2] = (unsigned short)q2; swq[rb + 3] = (unsigned short)q3;
    swq[rb + 4] = (unsigned short)q4; swq[rb + 5] = (unsigned short)q5;
    swq[rb + 6] = (unsigned short)q6; swq[rb + 7] = (unsigned short)q7;
    int ls = ((q0 + q1) + (q2 + q3)) + ((q4 + q5) + (q6 + q7));
#pragma unroll
    for (int o = 16; o; o >>= 1) ls += __shfl_xor_sync(~0u, ls, o);
    if ((t & 31) == 0) sredi[t >> 5] = ls;
    __syncthreads();
    if (t == 0) {
        int S = 0;
#pragma unroll
        for (int k = 0; k < 16; k++) S += sredi[k];
        sS = S;
    }
    __syncthreads();
    int S = sS;
    int Bc = (S + 19) / 20;            // first exact int cum >= Bc crosses
    float boundf = 0.05f * (float)S;   // value-space bound (q units)

    int w = t >> 5;
    int lane = t & 31;
    const uint4* tp = (const uint4*)g_tab;  // uint4 = 4 packed entries
    float* dst = out + slice * HW;

    // each warp walks groups r, r+GPB, ... independently (no syncs needed)
    for (int g = r; g < 256; g += GPB) {
        int p = (g << 4) + w;
        int row = p >> 6;
        int col = p & 63;
        int pbase2 = GUARD + (row + 63) * PITCH + col - 8064;

        int cum = 0;       // warp-uniform exact int running sum
        float accf = 0.f;  // per-lane distributed value accumulator

        for (int base = 0; base < NPAD; base += 256) {
            uint4 c0 = __ldg(tp + (base >> 2) + lane);       // seg0 entries
            uint4 c1 = __ldg(tp + (base >> 2) + 32 + lane);  // seg1 entries

            int qA = swq[pbase2 + (int)(c0.x & 0x3FFFu)];
            int qB = swq[pbase2 + (int)(c0.y & 0x3FFFu)];
            int qC = swq[pbase2 + (int)(c0.z & 0x3FFFu)];
            int qD = swq[pbase2 + (int)(c0.w & 0x3FFFu)];
            int qE = swq[pbase2 + (int)(c1.x & 0x3FFFu)];
            int qF = swq[pbase2 + (int)(c1.y & 0x3FFFu)];
            int qG = swq[pbase2 + (int)(c1.z & 0x3FFFu)];
            int qH = swq[pbase2 + (int)(c1.w & 0x3FFFu)];

            int mi0 = (qA + qB) + (qC + qD);
            int mi1 = (qE + qF) + (qG + qH);
            int tot = __reduce_add_sync(~0u, mi0 + mi1);  // one per 256

            if (cum + tot >= Bc) {  // exact: crossing inside these 256
                // segment-select, then single scan (lane's 4 contiguous)
                int s0 = mi0;
#pragma unroll
                for (int o = 1; o < 32; o <<= 1) {
                    int u = __shfl_up_sync(~0u, s0, o);
                    if (lane >= o) s0 += u;
                }
                int tot0 = __shfl_sync(~0u, s0, 31);
                uint4 cc;
                int b0, w0, w1, w2, w3;
                if (cum + tot0 >= Bc) {       // crossing in seg0
                    cc = c0;
                    b0 = cum + s0 - mi0;
                    w0 = qA; w1 = qB; w2 = qC; w3 = qD;
                } else {                      // all of seg0, cross in seg1
                    unsigned bs0 = (c0.x >> 14) * (unsigned)qA +
                                   (c0.y >> 14) * (unsigned)qB +
                                   (c0.z >> 14) * (unsigned)qC +
                                   (c0.w >> 14) * (unsigned)qD;
                    accf += (float)bs0;
                    int s1 = mi1;
#pragma unroll
                    for (int o = 1; o < 32; o <<= 1) {
                        int u = __shfl_up_sync(~0u, s1, o);
                        if (lane >= o) s1 += u;
                    }
                    cc = c1;
                    b0 = cum + tot0 + s1 - mi1;
                    w0 = qE; w1 = qF; w2 = qG; w3 = qH;
                }
                int e1 = b0 + w0, e2 = e1 + w1, e3 = e2 + w2, e4 = e3 + w3;
                unsigned m = __ballot_sync(~0u, e4 >= Bc);  // bit31 set
                int fl = __ffs(m) - 1;
                if (lane < fl) {
                    // full contribution of this lane's 4 segment entries
                    unsigned bsl = (cc.x >> 14) * (unsigned)w0 +
                                   (cc.y >> 14) * (unsigned)w1 +
                                   (cc.z >> 14) * (unsigned)w2 +
                                   (cc.w >> 14) * (unsigned)w3;
                    accf += (float)bsl;
                } else if (lane == fl) {
                    float fA = (float)(int)(cc.x >> 14);
                    float fB = (float)(int)(cc.y >> 14);
                    float fC = (float)(int)(cc.z >> 14);
                    float fD = (float)(int)(cc.w >> 14);
                    if (e1 >= Bc) {
                        accf += fA * (boundf - (float)b0);
                    } else {
                        accf += fA * (float)w0;
                        if (e2 >= Bc) {
                            accf += fB * (boundf - (float)e1);
                        } else {
                            accf += fB * (float)w1;
                            if (e3 >= Bc) {
                                accf += fC * (boundf - (float)e2);
                            } else {
                                accf += fC * (float)w2;
                                accf += fD * (boundf - (float)e3);
                            }
                        }
                    }
                }
                break;  // warp-uniform exit (crossing guaranteed: S >= Bc)
            }
            // non-crossing batch: lazy exact value accumulation
            cum += tot;
            unsigned bs0 = (c0.x >> 14) * (unsigned)qA +
                           (c0.y >> 14) * (unsigned)qB +
                           (c0.z >> 14) * (unsigned)qC +
                           (c0.w >> 14) * (unsigned)qD;
            unsigned bs1 = (c1.x >> 14) * (unsigned)qE +
                           (c1.y >> 14) * (unsigned)qF +
                           (c1.z >> 14) * (unsigned)qG +
                           (c1.w >> 14) * (unsigned)qH;
            accf += (float)bs0 + (float)bs1;
        }

#pragma unroll
        for (int o = 16; o; o >>= 1) accf += __shfl_xor_sync(~0u, accf, o);
        if (lane == 0) dst[p] = sqrtf(accf / boundf);
    }
}

extern "C" void kernel_launch(void* const* d_in, const int* in_sizes, int n_in,
                              void* d_out, int out_size) {
    const float* x = (const float*)d_in[0];
    float* out = (float*)d_out;

    k_build<<<(NPAD * 8) / 256, 256>>>();
    k_main<<<NSLICE * GPB, 512>>>(x, out);
}